// round 8
// baseline (speedup 1.0000x reference)
#include <cuda_runtime.h>
#include <cuda_fp16.h>
#include <cstdint>

#define EMBED   1024
#define NHEAD   16
#define HD      64
#define SEQ     2048
#define BATCH   4
#define MROWS   (BATCH * SEQ)      /* 8192 */
#define QKVN    (3 * EMBED)        /* 3072 */
#define KDIM    1024

// ---------------------------------------------------------------------------
// Scratch (device globals -- runtime allocation is forbidden)
// ---------------------------------------------------------------------------
static __device__ __half g_x2  [(size_t)MROWS * 2 * KDIM];   // x hi|lo
static __device__ __half g_qkv2[(size_t)MROWS * 2 * QKVN];   // qkv hi|lo
static __device__ __half g_att2[(size_t)MROWS * 2 * KDIM];   // attn out hi|lo
static __device__ __half g_wq2 [(size_t)QKVN  * KDIM];       // w_qkv^T fp16
static __device__ __half g_wo2 [(size_t)EMBED * KDIM];       // w_out^T fp16

// ---------------------------------------------------------------------------
// PTX helpers (baseline ISA, sm_80-compatible encodings only)
// ---------------------------------------------------------------------------
__device__ __forceinline__ uint32_t smem_u32(const void* p) {
    uint32_t a;
    asm("{ .reg .u64 t; cvta.to.shared.u64 t, %1; cvt.u32.u64 %0, t; }"
        : "=r"(a) : "l"(p));
    return a;
}
__device__ __forceinline__ void cpasync16(uint32_t dst, const void* src) {
    asm volatile("cp.async.cg.shared.global [%0], [%1], 16;"
        :: "r"(dst), "l"(src) : "memory");
}
#define CP_COMMIT() asm volatile("cp.async.commit_group;" ::: "memory")

__device__ __forceinline__ void ldsm4(uint32_t* r, uint32_t addr) {
    asm volatile("ldmatrix.sync.aligned.m8n8.x4.shared.b16 {%0,%1,%2,%3}, [%4];"
        : "=r"(r[0]), "=r"(r[1]), "=r"(r[2]), "=r"(r[3]) : "r"(addr));
}
__device__ __forceinline__ void ldsm4t(uint32_t* r, uint32_t addr) {
    asm volatile("ldmatrix.sync.aligned.m8n8.x4.trans.shared.b16 {%0,%1,%2,%3}, [%4];"
        : "=r"(r[0]), "=r"(r[1]), "=r"(r[2]), "=r"(r[3]) : "r"(addr));
}
// fp16 MMA, fp32 accumulate
__device__ __forceinline__ void mma16816(float* c, const uint32_t* a,
                                         uint32_t b0, uint32_t b1) {
    asm volatile(
        "mma.sync.aligned.m16n8k16.row.col.f32.f16.f16.f32 "
        "{%0,%1,%2,%3}, {%4,%5,%6,%7}, {%8,%9}, {%0,%1,%2,%3};"
        : "+f"(c[0]), "+f"(c[1]), "+f"(c[2]), "+f"(c[3])
        : "r"(a[0]), "r"(a[1]), "r"(a[2]), "r"(a[3]), "r"(b0), "r"(b1));
}
__device__ __forceinline__ float ex2(float x) {
    float y; asm("ex2.approx.f32 %0, %1;" : "=f"(y) : "f"(x)); return y;
}

__device__ __forceinline__ void split1h(float v, __half& h, __half& l) {
    h = __float2half_rn(v);
    l = __float2half_rn(v - __half2float(h));
}
// split a float pair into packed-fp16x2 hi and lo words
__device__ __forceinline__ void pack_split(float x, float y, uint32_t& hi, uint32_t& lo) {
    __half2 h = __floats2half2_rn(x, y);
    float hx = __low2float(h), hy = __high2float(h);
    __half2 l = __floats2half2_rn(x - hx, y - hy);
    hi = *(uint32_t*)&h; lo = *(uint32_t*)&l;
}

// ---------------------------------------------------------------------------
// operand prep
// ---------------------------------------------------------------------------
// in [M, K] fp32 -> out [M, 2K] fp16 : [hi | lo]
__global__ void split_rows(const float* __restrict__ in, __half* __restrict__ out) {
    size_t i4 = (size_t)blockIdx.x * blockDim.x + threadIdx.x;
    size_t row = i4 / (KDIM / 4);
    int    c   = (int)(i4 % (KDIM / 4)) << 2;
    float4 v = *(const float4*)(in + row * KDIM + c);
    __half h0, h1, h2, h3, l0, l1, l2, l3;
    split1h(v.x, h0, l0); split1h(v.y, h1, l1);
    split1h(v.z, h2, l2); split1h(v.w, h3, l3);
    __half* oh = out + row * (2 * KDIM) + c;
    __half* ol = oh + KDIM;
    *(__half2*)(oh)     = __halves2half2(h0, h1);
    *(__half2*)(oh + 2) = __halves2half2(h2, h3);
    *(__half2*)(ol)     = __halves2half2(l0, l1);
    *(__half2*)(ol + 2) = __halves2half2(l2, l3);
}

// w [K, N] fp32 -> out [N, K] fp16 (transpose + cast)
__global__ __launch_bounds__(256) void castT(const float* __restrict__ w,
                                             __half* __restrict__ out, int N) {
    __shared__ float t[32][33];
    const int tid = threadIdx.x;
    const int tx = tid & 31, ty = tid >> 5;
    const int n0 = blockIdx.x * 32, k0 = blockIdx.y * 32;
#pragma unroll
    for (int i = 0; i < 4; i++)
        t[ty + 8 * i][tx] = w[(size_t)(k0 + ty + 8 * i) * N + n0 + tx];
    __syncthreads();
#pragma unroll
    for (int i = 0; i < 4; i++) {
        int nl = ty + 8 * i;
        out[(size_t)(n0 + nl) * KDIM + k0 + tx] = __float2half_rn(t[tx][nl]);
    }
}

// ---------------------------------------------------------------------------
// mma.sync fp16x2 GEMM v3: CTA 128x256, warp tile 64x64 (2Mx4N warps).
// A [M,2K] fp16 hi|lo, B [N,K] fp16. 2 MMA terms per k16: ah*b + al*b.
// BK=64, 3-stage cp.async. Stage 64KB: A_hi 16K | A_lo 16K | B 32K.
// Rows 128B, chunk swizzle c^(r&7).
//   SPLIT=false: C fp32 [M,ldc] + bias
//   SPLIT=true : C fp16 [M,ldc], hi at col, lo at col+3072, + bias
// ---------------------------------------------------------------------------
#define BM 128
#define BN 256
#define BK 64
#define NK (KDIM / BK)            /* 16 */
#define NSTAGE 3
#define STG_BYTES 65536
#define GEMM_SMEM (NSTAGE * STG_BYTES)   /* 196608 */

__device__ __forceinline__ void gemm_load_stage(
    uint32_t sbase, const __half* __restrict__ A2,
    const __half* __restrict__ B1, int m0, int n0, int kt, int tid)
{
    const int k0 = kt * BK;
#pragma unroll
    for (int i = 0; i < 4; i++) {          // A: 128 rows x 8 chunks, hi+lo
        int id = tid + 256 * i;
        int r = id >> 3;
        int c = id & 7;
        uint32_t soff = r * 128 + ((c ^ (r & 7)) << 4);
        const __half* ga = A2 + (size_t)(m0 + r) * (2 * KDIM) + k0 + c * 8;
        cpasync16(sbase + soff,         ga);            // A hi
        cpasync16(sbase + 16384 + soff, ga + KDIM);     // A lo
    }
#pragma unroll
    for (int j = 0; j < 8; j++) {          // B: 256 rows x 8 chunks
        int id = tid + 256 * j;
        int r = id >> 3;
        int c = id & 7;
        uint32_t soff = r * 128 + ((c ^ (r & 7)) << 4);
        cpasync16(sbase + 32768 + soff,
                  B1 + (size_t)(n0 + r) * KDIM + k0 + c * 8);
    }
}

template<bool SPLIT>
__global__ __launch_bounds__(256, 1) void mma_gemm(
    const __half* __restrict__ A2, const __half* __restrict__ B1,
    const float* __restrict__ bias, void* __restrict__ Cv, int ldc)
{
    extern __shared__ char sm[];
    const uint32_t sb = smem_u32(sm);
    const int tid  = threadIdx.x;
    const int lane = tid & 31;
    const int wid  = tid >> 5;
    const int wm   = wid & 1;          // 2 warps over M (64 rows each)
    const int wn   = wid >> 1;         // 4 warps over N (64 cols each)
    const int m0 = blockIdx.y * BM;
    const int n0 = blockIdx.x * BN;

    const int lrow  = lane & 15;
    const int lhalf = lane >> 4;
    const int xorv  = lrow & 7;

    uint32_t arow[4], brow[4];
#pragma unroll
    for (int mt = 0; mt < 4; mt++) arow[mt] = (wm * 64 + mt * 16 + lrow) * 128;
#pragma unroll
    for (int nt2 = 0; nt2 < 4; nt2++)
        brow[nt2] = 32768u + (wn * 64 + nt2 * 16 + lrow) * 128;

    float acc[4][8][4];
#pragma unroll
    for (int i = 0; i < 4; i++)
#pragma unroll
        for (int j = 0; j < 8; j++)
#pragma unroll
            for (int q = 0; q < 4; q++) acc[i][j][q] = 0.f;

    gemm_load_stage(sb,             A2, B1, m0, n0, 0, tid); CP_COMMIT();
    gemm_load_stage(sb + STG_BYTES, A2, B1, m0, n0, 1, tid); CP_COMMIT();

    for (int kt = 0; kt < NK; kt++) {
        if (kt < NK - 2) {
            gemm_load_stage(sb + ((kt + 2) % NSTAGE) * STG_BYTES, A2, B1, m0, n0, kt + 2, tid);
            CP_COMMIT();
            asm volatile("cp.async.wait_group 2;" ::: "memory");
        } else if (kt == NK - 2) {
            asm volatile("cp.async.wait_group 1;" ::: "memory");
        } else {
            asm volatile("cp.async.wait_group 0;" ::: "memory");
        }
        __syncthreads();

        const uint32_t st = sb + (kt % NSTAGE) * STG_BYTES;
#pragma unroll
        for (int ks = 0; ks < 4; ks++) {
            const uint32_t coff = (uint32_t)(((ks * 2 + lhalf) ^ xorv) << 4);
            uint32_t bh[4][4];
#pragma unroll
            for (int nt2 = 0; nt2 < 4; nt2++) ldsm4(bh[nt2], st + brow[nt2] + coff);

            uint32_t ah[4][4];
#pragma unroll
            for (int mt = 0; mt < 4; mt++) ldsm4(ah[mt], st + arow[mt] + coff);
#pragma unroll
            for (int mt = 0; mt < 4; mt++)
#pragma unroll
                for (int nt = 0; nt < 8; nt++) {
                    const int n2 = nt >> 1, sel = nt & 1;
                    mma16816(acc[mt][nt], ah[mt], bh[n2][sel], bh[n2][sel + 2]);
                }

            uint32_t al[4][4];
#pragma unroll
            for (int mt = 0; mt < 4; mt++) ldsm4(al[mt], st + 16384 + arow[mt] + coff);
#pragma unroll
            for (int mt = 0; mt < 4; mt++)
#pragma unroll
                for (int nt = 0; nt < 8; nt++) {
                    const int n2 = nt >> 1, sel = nt & 1;
                    mma16816(acc[mt][nt], al[mt], bh[n2][sel], bh[n2][sel + 2]);
                }
        }
        __syncthreads();
    }

#pragma unroll
    for (int nt = 0; nt < 8; nt++) {
        const int col = n0 + wn * 64 + nt * 8 + (lane & 3) * 2;
        const float bx = __ldg(bias + col);
        const float by = __ldg(bias + col + 1);
#pragma unroll
        for (int mt = 0; mt < 4; mt++) {
            const int row = m0 + wm * 64 + mt * 16 + (lane >> 2);
            if (SPLIT) {
                __half* Cb = (__half*)Cv;
                uint32_t hi, lo;
                pack_split(acc[mt][nt][0] + bx, acc[mt][nt][1] + by, hi, lo);
                __half* p = Cb + (size_t)row * ldc + col;
                *(uint32_t*)p = hi; *(uint32_t*)(p + QKVN) = lo;
                pack_split(acc[mt][nt][2] + bx, acc[mt][nt][3] + by, hi, lo);
                p = Cb + (size_t)(row + 8) * ldc + col;
                *(uint32_t*)p = hi; *(uint32_t*)(p + QKVN) = lo;
            } else {
                float* C = (float*)Cv;
                float2 v0 = make_float2(acc[mt][nt][0] + bx, acc[mt][nt][1] + by);
                float2 v1 = make_float2(acc[mt][nt][2] + bx, acc[mt][nt][3] + by);
                *(float2*)(C + (size_t)row * ldc + col)       = v0;
                *(float2*)(C + (size_t)(row + 8) * ldc + col) = v1;
            }
        }
    }
}

// ---------------------------------------------------------------------------
// Tensor-core flash attention (fp16x2) -- unchanged from R7 (passing)
// ---------------------------------------------------------------------------
#define AT_SMEM (32768 + 2 * 16384)   /* 65536 */
#define C1 0.18033688f                /* 0.125 * log2(e) */

__device__ __forceinline__ void attn_load_kv(
    uint32_t stage, const __half* __restrict__ kvb, int tid)
{
#pragma unroll
    for (int i = 0; i < 2; i++) {
        int id = tid + 256 * i;            // 0..511 -> 64 rows x 8 chunks
        int r = id >> 3, c = id & 7;
        uint32_t soff = r * 128 + ((c ^ (r & 7)) << 4);
        const __half* g = kvb + (size_t)r * 6144 + c * 8;
        cpasync16(stage +        soff, g + 1024);   // K hi
        cpasync16(stage + 8192 + soff, g + 2048);   // V hi
    }
}

__global__ __launch_bounds__(256, 1) void attn_mma(
    const __half* __restrict__ qkv2, __half* __restrict__ att2)
{
    extern __shared__ char sm[];
    const uint32_t sb = smem_u32(sm);
    const uint32_t Qh = sb, Ql = sb + 16384, ST0 = sb + 32768;

    const int tid = threadIdx.x, lane = tid & 31, wid = tid >> 5;
    const int qb = blockIdx.x, h = blockIdx.y, b = blockIdx.z;
    const int lrow = lane & 15, lhalf = lane >> 4;
    const size_t rowbase = (size_t)b * SEQ;
    const __half* qg  = qkv2 + (rowbase + qb * 128) * 6144 + h * 64;
    const __half* kvg = qkv2 + rowbase * 6144 + h * 64;

    // Q tile loads (hi+lo)
#pragma unroll
    for (int i = 0; i < 4; i++) {
        int id = tid + 256 * i;            // 0..1023 -> 128 rows x 8 chunks
        int r = id >> 3, c = id & 7;
        uint32_t soff = r * 128 + ((c ^ (r & 7)) << 4);
        const __half* g = qg + (size_t)r * 6144 + c * 8;
        cpasync16(Qh + soff, g);
        cpasync16(Ql + soff, g + 3072);
    }
    CP_COMMIT();
    attn_load_kv(ST0,         kvg,             tid); CP_COMMIT();
    attn_load_kv(ST0 + 16384, kvg + 64 * 6144, tid); CP_COMMIT();

    // Q fragments to registers
    asm volatile("cp.async.wait_group 2;" ::: "memory");
    __syncthreads();
    uint32_t qfh[4][4], qfl[4][4];
    {
        int r = wid * 16 + lrow;
        uint32_t ro = (uint32_t)r * 128;
        int xv = r & 7;
#pragma unroll
        for (int ds = 0; ds < 4; ds++) {
            uint32_t co = (uint32_t)(((ds * 2 + lhalf) ^ xv) << 4);
            ldsm4(qfh[ds], Qh + ro + co);
            ldsm4(qfl[ds], Ql + ro + co);
        }
    }

    float oacc[8][4];
#pragma unroll
    for (int t = 0; t < 8; t++)
#pragma unroll
        for (int q = 0; q < 4; q++) oacc[t][q] = 0.f;
    float m0 = -1e30f, m1 = -1e30f, l0 = 0.f, l1 = 0.f;

    const int kxv = lrow & 7;
    for (int kt = 0; kt < 32; kt++) {
        if (kt == 31) asm volatile("cp.async.wait_group 0;" ::: "memory");
        else          asm volatile("cp.async.wait_group 1;" ::: "memory");
        __syncthreads();
        const uint32_t st = ST0 + (uint32_t)(kt & 1) * 16384;

        // ---- S = Q K^T (2-term split)
        float sacc[8][4];
#pragma unroll
        for (int t = 0; t < 8; t++)
#pragma unroll
            for (int q = 0; q < 4; q++) sacc[t][q] = 0.f;

#pragma unroll
        for (int ds = 0; ds < 4; ds++) {
            uint32_t kh[4][4];
            const uint32_t co = (uint32_t)(((ds * 2 + lhalf) ^ kxv) << 4);
#pragma unroll
            for (int g = 0; g < 4; g++)
                ldsm4(kh[g], st + (uint32_t)(g * 16 + lrow) * 128 + co);
#pragma unroll
            for (int g = 0; g < 4; g++)
#pragma unroll
                for (int sel = 0; sel < 2; sel++) {
                    float* c = sacc[g * 2 + sel];
                    mma16816(c, qfh[ds], kh[g][sel], kh[g][sel + 2]);
                    mma16816(c, qfl[ds], kh[g][sel], kh[g][sel + 2]);
                }
        }

        // ---- online softmax
        float mx0 = sacc[0][0], mx1 = sacc[0][2];
#pragma unroll
        for (int t = 0; t < 8; t++) {
            mx0 = fmaxf(mx0, fmaxf(sacc[t][0], sacc[t][1]));
            mx1 = fmaxf(mx1, fmaxf(sacc[t][2], sacc[t][3]));
        }
        mx0 = fmaxf(mx0, __shfl_xor_sync(0xffffffffu, mx0, 1));
        mx0 = fmaxf(mx0, __shfl_xor_sync(0xffffffffu, mx0, 2));
        mx1 = fmaxf(mx1, __shfl_xor_sync(0xffffffffu, mx1, 1));
        mx1 = fmaxf(mx1, __shfl_xor_sync(0xffffffffu, mx1, 2));
        const float mn0 = fmaxf(m0, mx0), mn1 = fmaxf(m1, mx1);
        const float a0 = ex2((m0 - mn0) * C1), a1 = ex2((m1 - mn1) * C1);
        const float mc0 = mn0 * C1, mc1 = mn1 * C1;
        float ls0 = 0.f, ls1 = 0.f;
#pragma unroll
        for (int t = 0; t < 8; t++) {
            sacc[t][0] = ex2(fmaf(sacc[t][0], C1, -mc0));
            sacc[t][1] = ex2(fmaf(sacc[t][1], C1, -mc0));
            sacc[t][2] = ex2(fmaf(sacc[t][2], C1, -mc1));
            sacc[t][3] = ex2(fmaf(sacc[t][3], C1, -mc1));
            ls0 += sacc[t][0] + sacc[t][1];
            ls1 += sacc[t][2] + sacc[t][3];
        }
        ls0 += __shfl_xor_sync(0xffffffffu, ls0, 1);
        ls0 += __shfl_xor_sync(0xffffffffu, ls0, 2);
        ls1 += __shfl_xor_sync(0xffffffffu, ls1, 1);
        ls1 += __shfl_xor_sync(0xffffffffu, ls1, 2);
        m0 = mn0; m1 = mn1;
        l0 = l0 * a0 + ls0; l1 = l1 * a1 + ls1;
#pragma unroll
        for (int t = 0; t < 8; t++) {
            oacc[t][0] *= a0; oacc[t][1] *= a0;
            oacc[t][2] *= a1; oacc[t][3] *= a1;
        }

        // ---- O += P V (2-term split; P packed in registers)
#pragma unroll
        for (int kg = 0; kg < 4; kg++) {
            uint32_t aph[4], apl[4];
            {
                const float* t0 = sacc[2 * kg];
                const float* t1 = sacc[2 * kg + 1];
                pack_split(t0[0], t0[1], aph[0], apl[0]);
                pack_split(t0[2], t0[3], aph[1], apl[1]);
                pack_split(t1[0], t1[1], aph[2], apl[2]);
                pack_split(t1[2], t1[3], aph[3], apl[3]);
            }
            const uint32_t vro = st + 8192 + (uint32_t)(kg * 16 + lrow) * 128;
#pragma unroll
            for (int dg = 0; dg < 4; dg++) {
                uint32_t vh[4];
                ldsm4t(vh, vro + (uint32_t)(((dg * 2 + lhalf) ^ kxv) << 4));
#pragma unroll
                for (int sel = 0; sel < 2; sel++) {
                    float* c = oacc[dg * 2 + sel];
                    mma16816(c, aph, vh[2 * sel], vh[2 * sel + 1]);
                    mma16816(c, apl, vh[2 * sel], vh[2 * sel + 1]);
                }
            }
        }
        __syncthreads();
        if (kt + 2 < 32) {
            attn_load_kv(ST0 + (uint32_t)(kt & 1) * 16384,
                         kvg + (size_t)(kt + 2) * 64 * 6144, tid);
            CP_COMMIT();
        }
    }

    // ---- epilogue: normalize, split to fp16 hi/lo, store
    const float inv0 = 1.0f / l0, inv1 = 1.0f / l1;
    const size_t grow = rowbase + (size_t)qb * 128 + wid * 16 + (lane >> 2);
#pragma unroll
    for (int t = 0; t < 8; t++) {
        const int col = h * 64 + t * 8 + (lane & 3) * 2;
        uint32_t hi, lo;
        pack_split(oacc[t][0] * inv0, oacc[t][1] * inv0, hi, lo);
        __half* p = att2 + grow * 2048 + col;
        *(uint32_t*)p = hi; *(uint32_t*)(p + 1024) = lo;
        pack_split(oacc[t][2] * inv1, oacc[t][3] * inv1, hi, lo);
        p = att2 + (grow + 8) * 2048 + col;
        *(uint32_t*)p = hi; *(uint32_t*)(p + 1024) = lo;
    }
}

// ---------------------------------------------------------------------------
// Host side
// ---------------------------------------------------------------------------
extern "C" void kernel_launch(void* const* d_in, const int* in_sizes, int n_in,
                              void* d_out, int out_size)
{
    (void)in_sizes; (void)n_in; (void)out_size;
    const float* x     = (const float*)d_in[0];
    const float* w_qkv = (const float*)d_in[1];
    const float* b_qkv = (const float*)d_in[2];
    const float* w_out = (const float*)d_in[3];
    const float* b_out = (const float*)d_in[4];
    float* out = (float*)d_out;

    __half *x2, *qkv2, *att2, *wq2, *wo2;
    cudaGetSymbolAddress((void**)&x2,   g_x2);
    cudaGetSymbolAddress((void**)&qkv2, g_qkv2);
    cudaGetSymbolAddress((void**)&att2, g_att2);
    cudaGetSymbolAddress((void**)&wq2,  g_wq2);
    cudaGetSymbolAddress((void**)&wo2,  g_wo2);

    cudaFuncSetAttribute(mma_gemm<true>,  cudaFuncAttributeMaxDynamicSharedMemorySize, GEMM_SMEM);
    cudaFuncSetAttribute(mma_gemm<false>, cudaFuncAttributeMaxDynamicSharedMemorySize, GEMM_SMEM);
    cudaFuncSetAttribute(attn_mma, cudaFuncAttributeMaxDynamicSharedMemorySize, AT_SMEM);

    // 1) operand prep
    split_rows<<<(MROWS * KDIM / 4) / 256, 256>>>(x, x2);
    castT<<<dim3(QKVN / 32, KDIM / 32), 256>>>(w_qkv, wq2, QKVN);
    castT<<<dim3(EMBED / 32, KDIM / 32), 256>>>(w_out, wo2, EMBED);

    // 2) QKV projection -> split fp16 qkv
    mma_gemm<true><<<dim3(QKVN / BN, MROWS / BM), 256, GEMM_SMEM>>>(
        x2, wq2, b_qkv, qkv2, 2 * QKVN);

    // 3) tensor-core flash attention -> split fp16 att
    attn_mma<<<dim3(SEQ / 128, NHEAD, BATCH), 256, AT_SMEM>>>(qkv2, att2);

    // 4) output projection -> fp32 out
    mma_gemm<false><<<dim3(EMBED / BN, MROWS / BM), 256, GEMM_SMEM>>>(
        att2, wo2, b_out, out, EMBED);
}

// round 9
// speedup vs baseline: 1.3988x; 1.3988x over previous
#include <cuda_runtime.h>
#include <cuda_fp16.h>
#include <cstdint>

#define EMBED   1024
#define NHEAD   16
#define HD      64
#define SEQ     2048
#define BATCH   4
#define MROWS   (BATCH * SEQ)      /* 8192 */
#define QKVN    (3 * EMBED)        /* 3072 */
#define KDIM    1024

// ---------------------------------------------------------------------------
// Scratch (device globals -- runtime allocation is forbidden)
// ---------------------------------------------------------------------------
static __device__ __half g_x2  [(size_t)MROWS * 2 * KDIM];   // x hi|lo
static __device__ __half g_qkv1[(size_t)MROWS * QKVN];       // qkv fp16 single
static __device__ __half g_att1[(size_t)MROWS * KDIM];       // attn out fp16 single
static __device__ __half g_wq2 [(size_t)QKVN  * KDIM];       // w_qkv^T fp16
static __device__ __half g_wo2 [(size_t)EMBED * KDIM];       // w_out^T fp16

// ---------------------------------------------------------------------------
// PTX helpers (baseline ISA, sm_80-compatible encodings only)
// ---------------------------------------------------------------------------
__device__ __forceinline__ uint32_t smem_u32(const void* p) {
    uint32_t a;
    asm("{ .reg .u64 t; cvta.to.shared.u64 t, %1; cvt.u32.u64 %0, t; }"
        : "=r"(a) : "l"(p));
    return a;
}
__device__ __forceinline__ void cpasync16(uint32_t dst, const void* src) {
    asm volatile("cp.async.cg.shared.global [%0], [%1], 16;"
        :: "r"(dst), "l"(src) : "memory");
}
#define CP_COMMIT() asm volatile("cp.async.commit_group;" ::: "memory")

__device__ __forceinline__ void ldsm4(uint32_t* r, uint32_t addr) {
    asm volatile("ldmatrix.sync.aligned.m8n8.x4.shared.b16 {%0,%1,%2,%3}, [%4];"
        : "=r"(r[0]), "=r"(r[1]), "=r"(r[2]), "=r"(r[3]) : "r"(addr));
}
__device__ __forceinline__ void ldsm4t(uint32_t* r, uint32_t addr) {
    asm volatile("ldmatrix.sync.aligned.m8n8.x4.trans.shared.b16 {%0,%1,%2,%3}, [%4];"
        : "=r"(r[0]), "=r"(r[1]), "=r"(r[2]), "=r"(r[3]) : "r"(addr));
}
// fp16 MMA, fp32 accumulate
__device__ __forceinline__ void mma16816(float* c, const uint32_t* a,
                                         uint32_t b0, uint32_t b1) {
    asm volatile(
        "mma.sync.aligned.m16n8k16.row.col.f32.f16.f16.f32 "
        "{%0,%1,%2,%3}, {%4,%5,%6,%7}, {%8,%9}, {%0,%1,%2,%3};"
        : "+f"(c[0]), "+f"(c[1]), "+f"(c[2]), "+f"(c[3])
        : "r"(a[0]), "r"(a[1]), "r"(a[2]), "r"(a[3]), "r"(b0), "r"(b1));
}
__device__ __forceinline__ float ex2(float x) {
    float y; asm("ex2.approx.f32 %0, %1;" : "=f"(y) : "f"(x)); return y;
}

__device__ __forceinline__ void split1h(float v, __half& h, __half& l) {
    h = __float2half_rn(v);
    l = __float2half_rn(v - __half2float(h));
}
__device__ __forceinline__ uint32_t pack_h2(float x, float y) {
    __half2 h = __floats2half2_rn(x, y);
    return *(uint32_t*)&h;
}

// ---------------------------------------------------------------------------
// operand prep
// ---------------------------------------------------------------------------
// in [M, K] fp32 -> out [M, 2K] fp16 : [hi | lo]
__global__ void split_rows(const float* __restrict__ in, __half* __restrict__ out) {
    size_t i4 = (size_t)blockIdx.x * blockDim.x + threadIdx.x;
    size_t row = i4 / (KDIM / 4);
    int    c   = (int)(i4 % (KDIM / 4)) << 2;
    float4 v = *(const float4*)(in + row * KDIM + c);
    __half h0, h1, h2, h3, l0, l1, l2, l3;
    split1h(v.x, h0, l0); split1h(v.y, h1, l1);
    split1h(v.z, h2, l2); split1h(v.w, h3, l3);
    __half* oh = out + row * (2 * KDIM) + c;
    __half* ol = oh + KDIM;
    *(__half2*)(oh)     = __halves2half2(h0, h1);
    *(__half2*)(oh + 2) = __halves2half2(h2, h3);
    *(__half2*)(ol)     = __halves2half2(l0, l1);
    *(__half2*)(ol + 2) = __halves2half2(l2, l3);
}

// w [K, N] fp32 -> out [N, K] fp16 (transpose + cast)
__global__ __launch_bounds__(256) void castT(const float* __restrict__ w,
                                             __half* __restrict__ out, int N) {
    __shared__ float t[32][33];
    const int tid = threadIdx.x;
    const int tx = tid & 31, ty = tid >> 5;
    const int n0 = blockIdx.x * 32, k0 = blockIdx.y * 32;
#pragma unroll
    for (int i = 0; i < 4; i++)
        t[ty + 8 * i][tx] = w[(size_t)(k0 + ty + 8 * i) * N + n0 + tx];
    __syncthreads();
#pragma unroll
    for (int i = 0; i < 4; i++) {
        int nl = ty + 8 * i;
        out[(size_t)(n0 + nl) * KDIM + k0 + tx] = __float2half_rn(t[tx][nl]);
    }
}

// ---------------------------------------------------------------------------
// mma.sync fp16 GEMM. CTA 128x128, warp tile 64x32 (2Mx4N warps), BK=64,
// 3-stage cp.async, chunk swizzle c^(r&7).
// ALO=true : A [M,2K] hi|lo, 2 MMA terms (ah*b + al*b). Stage 48KB.
// ALO=false: A [M,K] single, 1 MMA term.                Stage 32KB.
// SPLIT=true : C fp16 [M,ldc] + bias.   SPLIT=false: C fp32 [M,ldc] + bias.
// ---------------------------------------------------------------------------
#define BM 128
#define BN 128
#define BK 64
#define NK (KDIM / BK)            /* 16 */
#define NSTAGE 3

template<bool ALO>
__device__ __forceinline__ void gemm_load_stage(
    uint32_t sbase, const __half* __restrict__ A, const __half* __restrict__ B1,
    int m0, int n0, int kt, int tid)
{
    const int k0 = kt * BK;
    const uint32_t boff = ALO ? 32768u : 16384u;
    const int astride = ALO ? 2 * KDIM : KDIM;
#pragma unroll
    for (int i = 0; i < 4; i++) {
        int id = tid + 256 * i;            // 0..1023: 128 rows x 8 chunks
        int r = id >> 3;
        int c = id & 7;
        uint32_t soff = r * 128 + ((c ^ (r & 7)) << 4);
        const __half* ga = A + (size_t)(m0 + r) * astride + k0 + c * 8;
        cpasync16(sbase + soff, ga);                       // A hi
        if (ALO) cpasync16(sbase + 16384 + soff, ga + KDIM);  // A lo
        cpasync16(sbase + boff + soff,
                  B1 + (size_t)(n0 + r) * KDIM + k0 + c * 8);  // B
    }
}

template<bool SPLIT, bool ALO>
__global__ __launch_bounds__(256, 1) void mma_gemm(
    const __half* __restrict__ A, const __half* __restrict__ B1,
    const float* __restrict__ bias, void* __restrict__ Cv, int ldc)
{
    constexpr uint32_t STG  = ALO ? 49152u : 32768u;
    constexpr uint32_t BOFF = ALO ? 32768u : 16384u;
    extern __shared__ char sm[];
    const uint32_t sb = smem_u32(sm);
    const int tid  = threadIdx.x;
    const int lane = tid & 31;
    const int wid  = tid >> 5;
    const int wm   = wid & 1;
    const int wn   = wid >> 1;
    const int m0 = blockIdx.y * BM;
    const int n0 = blockIdx.x * BN;

    const int lrow  = lane & 15;
    const int lhalf = lane >> 4;
    const int xorv  = lrow & 7;

    uint32_t arow[4], brow[2];
#pragma unroll
    for (int mt = 0; mt < 4; mt++) arow[mt] = (wm * 64 + mt * 16 + lrow) * 128;
#pragma unroll
    for (int nt2 = 0; nt2 < 2; nt2++)
        brow[nt2] = BOFF + (wn * 32 + nt2 * 16 + lrow) * 128;

    float acc[4][4][4];
#pragma unroll
    for (int i = 0; i < 4; i++)
#pragma unroll
        for (int j = 0; j < 4; j++)
#pragma unroll
            for (int q = 0; q < 4; q++) acc[i][j][q] = 0.f;

    gemm_load_stage<ALO>(sb,       A, B1, m0, n0, 0, tid); CP_COMMIT();
    gemm_load_stage<ALO>(sb + STG, A, B1, m0, n0, 1, tid); CP_COMMIT();

    for (int kt = 0; kt < NK; kt++) {
        if (kt < NK - 2) {
            gemm_load_stage<ALO>(sb + ((kt + 2) % NSTAGE) * STG, A, B1, m0, n0, kt + 2, tid);
            CP_COMMIT();
            asm volatile("cp.async.wait_group 2;" ::: "memory");
        } else if (kt == NK - 2) {
            asm volatile("cp.async.wait_group 1;" ::: "memory");
        } else {
            asm volatile("cp.async.wait_group 0;" ::: "memory");
        }
        __syncthreads();

        const uint32_t st = sb + (kt % NSTAGE) * STG;
#pragma unroll
        for (int ks = 0; ks < 4; ks++) {
            const uint32_t coff = (uint32_t)(((ks * 2 + lhalf) ^ xorv) << 4);
            uint32_t ah[4][4], bh[2][4];
#pragma unroll
            for (int mt = 0; mt < 4; mt++) ldsm4(ah[mt], st + arow[mt] + coff);
#pragma unroll
            for (int nt2 = 0; nt2 < 2; nt2++) ldsm4(bh[nt2], st + brow[nt2] + coff);
#pragma unroll
            for (int mt = 0; mt < 4; mt++)
#pragma unroll
                for (int nt = 0; nt < 4; nt++) {
                    const int n2 = nt >> 1, sel = nt & 1;
                    mma16816(acc[mt][nt], ah[mt], bh[n2][sel], bh[n2][sel + 2]);
                }
            if (ALO) {
                uint32_t al[4][4];
#pragma unroll
                for (int mt = 0; mt < 4; mt++)
                    ldsm4(al[mt], st + 16384 + arow[mt] + coff);
#pragma unroll
                for (int mt = 0; mt < 4; mt++)
#pragma unroll
                    for (int nt = 0; nt < 4; nt++) {
                        const int n2 = nt >> 1, sel = nt & 1;
                        mma16816(acc[mt][nt], al[mt], bh[n2][sel], bh[n2][sel + 2]);
                    }
            }
        }
        __syncthreads();
    }

#pragma unroll
    for (int nt = 0; nt < 4; nt++) {
        const int col = n0 + wn * 32 + nt * 8 + (lane & 3) * 2;
        const float bx = __ldg(bias + col);
        const float by = __ldg(bias + col + 1);
#pragma unroll
        for (int mt = 0; mt < 4; mt++) {
            const int row = m0 + wm * 64 + mt * 16 + (lane >> 2);
            if (SPLIT) {
                __half* Cb = (__half*)Cv;
                *(uint32_t*)(Cb + (size_t)row * ldc + col) =
                    pack_h2(acc[mt][nt][0] + bx, acc[mt][nt][1] + by);
                *(uint32_t*)(Cb + (size_t)(row + 8) * ldc + col) =
                    pack_h2(acc[mt][nt][2] + bx, acc[mt][nt][3] + by);
            } else {
                float* C = (float*)Cv;
                float2 v0 = make_float2(acc[mt][nt][0] + bx, acc[mt][nt][1] + by);
                float2 v1 = make_float2(acc[mt][nt][2] + bx, acc[mt][nt][3] + by);
                *(float2*)(C + (size_t)row * ldc + col)       = v0;
                *(float2*)(C + (size_t)(row + 8) * ldc + col) = v1;
            }
        }
    }
}

// ---------------------------------------------------------------------------
// Tensor-core flash attention, all-fp16 operands (single precision level).
// Per CTA: 128 q-rows, one (b,h). 8 warps x 16 rows. Key tiles of 64.
// smem: Q 16K | 2 stages of {K 8K | V 8K} = 48KB -> 2 CTAs/SM.
// qkv1 row layout: [q(1024) k(1024) v(1024)], row stride 3072.
// S = Q K^T (1 term); O += P V (1 term). Output att1 fp16 [row,1024].
// ---------------------------------------------------------------------------
#define AT_SMEM (16384 + 2 * 16384)   /* 49152 */
#define C1 0.18033688f                /* 0.125 * log2(e) */

__device__ __forceinline__ void attn_load_kv(
    uint32_t stage, const __half* __restrict__ kvb, int tid)
{
#pragma unroll
    for (int i = 0; i < 2; i++) {
        int id = tid + 256 * i;            // 0..511 -> 64 rows x 8 chunks
        int r = id >> 3, c = id & 7;
        uint32_t soff = r * 128 + ((c ^ (r & 7)) << 4);
        const __half* g = kvb + (size_t)r * 3072 + c * 8;
        cpasync16(stage +        soff, g + 1024);   // K
        cpasync16(stage + 8192 + soff, g + 2048);   // V
    }
}

__global__ __launch_bounds__(256, 2) void attn_mma(
    const __half* __restrict__ qkv1, __half* __restrict__ att1)
{
    extern __shared__ char sm[];
    const uint32_t sb = smem_u32(sm);
    const uint32_t Qs = sb, ST0 = sb + 16384;

    const int tid = threadIdx.x, lane = tid & 31, wid = tid >> 5;
    const int qb = blockIdx.x, h = blockIdx.y, b = blockIdx.z;
    const int lrow = lane & 15, lhalf = lane >> 4;
    const size_t rowbase = (size_t)b * SEQ;
    const __half* qg  = qkv1 + (rowbase + qb * 128) * 3072 + h * 64;
    const __half* kvg = qkv1 + rowbase * 3072 + h * 64;

    // Q tile load (single fp16)
#pragma unroll
    for (int i = 0; i < 4; i++) {
        int id = tid + 256 * i;            // 0..1023 -> 128 rows x 8 chunks
        int r = id >> 3, c = id & 7;
        uint32_t soff = r * 128 + ((c ^ (r & 7)) << 4);
        cpasync16(Qs + soff, qg + (size_t)r * 3072 + c * 8);
    }
    CP_COMMIT();
    attn_load_kv(ST0,         kvg,             tid); CP_COMMIT();
    attn_load_kv(ST0 + 16384, kvg + 64 * 3072, tid); CP_COMMIT();

    // Q fragments to registers
    asm volatile("cp.async.wait_group 2;" ::: "memory");
    __syncthreads();
    uint32_t qf[4][4];
    {
        int r = wid * 16 + lrow;
        uint32_t ro = (uint32_t)r * 128;
        int xv = r & 7;
#pragma unroll
        for (int ds = 0; ds < 4; ds++) {
            uint32_t co = (uint32_t)(((ds * 2 + lhalf) ^ xv) << 4);
            ldsm4(qf[ds], Qs + ro + co);
        }
    }

    float oacc[8][4];
#pragma unroll
    for (int t = 0; t < 8; t++)
#pragma unroll
        for (int q = 0; q < 4; q++) oacc[t][q] = 0.f;
    float m0 = -1e30f, m1 = -1e30f, l0 = 0.f, l1 = 0.f;

    const int kxv = lrow & 7;
    for (int kt = 0; kt < 32; kt++) {
        if (kt == 31) asm volatile("cp.async.wait_group 0;" ::: "memory");
        else          asm volatile("cp.async.wait_group 1;" ::: "memory");
        __syncthreads();
        const uint32_t st = ST0 + (uint32_t)(kt & 1) * 16384;

        // ---- S = Q K^T (single term)
        float sacc[8][4];
#pragma unroll
        for (int t = 0; t < 8; t++)
#pragma unroll
            for (int q = 0; q < 4; q++) sacc[t][q] = 0.f;

#pragma unroll
        for (int ds = 0; ds < 4; ds++) {
            uint32_t kh[4][4];
            const uint32_t co = (uint32_t)(((ds * 2 + lhalf) ^ kxv) << 4);
#pragma unroll
            for (int g = 0; g < 4; g++)
                ldsm4(kh[g], st + (uint32_t)(g * 16 + lrow) * 128 + co);
#pragma unroll
            for (int g = 0; g < 4; g++)
#pragma unroll
                for (int sel = 0; sel < 2; sel++)
                    mma16816(sacc[g * 2 + sel], qf[ds], kh[g][sel], kh[g][sel + 2]);
        }

        // ---- online softmax
        float mx0 = sacc[0][0], mx1 = sacc[0][2];
#pragma unroll
        for (int t = 0; t < 8; t++) {
            mx0 = fmaxf(mx0, fmaxf(sacc[t][0], sacc[t][1]));
            mx1 = fmaxf(mx1, fmaxf(sacc[t][2], sacc[t][3]));
        }
        mx0 = fmaxf(mx0, __shfl_xor_sync(0xffffffffu, mx0, 1));
        mx0 = fmaxf(mx0, __shfl_xor_sync(0xffffffffu, mx0, 2));
        mx1 = fmaxf(mx1, __shfl_xor_sync(0xffffffffu, mx1, 1));
        mx1 = fmaxf(mx1, __shfl_xor_sync(0xffffffffu, mx1, 2));
        const float mn0 = fmaxf(m0, mx0), mn1 = fmaxf(m1, mx1);
        const float a0 = ex2((m0 - mn0) * C1), a1 = ex2((m1 - mn1) * C1);
        const float mc0 = mn0 * C1, mc1 = mn1 * C1;
        float ls0 = 0.f, ls1 = 0.f;
#pragma unroll
        for (int t = 0; t < 8; t++) {
            sacc[t][0] = ex2(fmaf(sacc[t][0], C1, -mc0));
            sacc[t][1] = ex2(fmaf(sacc[t][1], C1, -mc0));
            sacc[t][2] = ex2(fmaf(sacc[t][2], C1, -mc1));
            sacc[t][3] = ex2(fmaf(sacc[t][3], C1, -mc1));
            ls0 += sacc[t][0] + sacc[t][1];
            ls1 += sacc[t][2] + sacc[t][3];
        }
        ls0 += __shfl_xor_sync(0xffffffffu, ls0, 1);
        ls0 += __shfl_xor_sync(0xffffffffu, ls0, 2);
        ls1 += __shfl_xor_sync(0xffffffffu, ls1, 1);
        ls1 += __shfl_xor_sync(0xffffffffu, ls1, 2);
        m0 = mn0; m1 = mn1;
        l0 = l0 * a0 + ls0; l1 = l1 * a1 + ls1;
#pragma unroll
        for (int t = 0; t < 8; t++) {
            oacc[t][0] *= a0; oacc[t][1] *= a0;
            oacc[t][2] *= a1; oacc[t][3] *= a1;
        }

        // ---- O += P V (single term; P packed in registers)
#pragma unroll
        for (int kg = 0; kg < 4; kg++) {
            uint32_t aph[4];
            {
                const float* t0 = sacc[2 * kg];
                const float* t1 = sacc[2 * kg + 1];
                aph[0] = pack_h2(t0[0], t0[1]);
                aph[1] = pack_h2(t0[2], t0[3]);
                aph[2] = pack_h2(t1[0], t1[1]);
                aph[3] = pack_h2(t1[2], t1[3]);
            }
            const uint32_t vro = st + 8192 + (uint32_t)(kg * 16 + lrow) * 128;
#pragma unroll
            for (int dg = 0; dg < 4; dg++) {
                uint32_t vh[4];
                ldsm4t(vh, vro + (uint32_t)(((dg * 2 + lhalf) ^ kxv) << 4));
#pragma unroll
                for (int sel = 0; sel < 2; sel++)
                    mma16816(oacc[dg * 2 + sel], aph, vh[2 * sel], vh[2 * sel + 1]);
            }
        }
        __syncthreads();
        if (kt + 2 < 32) {
            attn_load_kv(ST0 + (uint32_t)(kt & 1) * 16384,
                         kvg + (size_t)(kt + 2) * 64 * 3072, tid);
            CP_COMMIT();
        }
    }

    // ---- epilogue: normalize, cast fp16, store
    const float inv0 = 1.0f / l0, inv1 = 1.0f / l1;
    const size_t grow = rowbase + (size_t)qb * 128 + wid * 16 + (lane >> 2);
#pragma unroll
    for (int t = 0; t < 8; t++) {
        const int col = h * 64 + t * 8 + (lane & 3) * 2;
        *(uint32_t*)(att1 + grow * 1024 + col) =
            pack_h2(oacc[t][0] * inv0, oacc[t][1] * inv0);
        *(uint32_t*)(att1 + (grow + 8) * 1024 + col) =
            pack_h2(oacc[t][2] * inv1, oacc[t][3] * inv1);
    }
}

// ---------------------------------------------------------------------------
// Host side
// ---------------------------------------------------------------------------
extern "C" void kernel_launch(void* const* d_in, const int* in_sizes, int n_in,
                              void* d_out, int out_size)
{
    (void)in_sizes; (void)n_in; (void)out_size;
    const float* x     = (const float*)d_in[0];
    const float* w_qkv = (const float*)d_in[1];
    const float* b_qkv = (const float*)d_in[2];
    const float* w_out = (const float*)d_in[3];
    const float* b_out = (const float*)d_in[4];
    float* out = (float*)d_out;

    __half *x2, *qkv1, *att1, *wq2, *wo2;
    cudaGetSymbolAddress((void**)&x2,   g_x2);
    cudaGetSymbolAddress((void**)&qkv1, g_qkv1);
    cudaGetSymbolAddress((void**)&att1, g_att1);
    cudaGetSymbolAddress((void**)&wq2,  g_wq2);
    cudaGetSymbolAddress((void**)&wo2,  g_wo2);

    const int smem1 = NSTAGE * 49152;   // ALO=true
    const int smem2 = NSTAGE * 32768;   // ALO=false
    cudaFuncSetAttribute(mma_gemm<true, true>,
                         cudaFuncAttributeMaxDynamicSharedMemorySize, smem1);
    cudaFuncSetAttribute(mma_gemm<false, false>,
                         cudaFuncAttributeMaxDynamicSharedMemorySize, smem2);
    cudaFuncSetAttribute(attn_mma, cudaFuncAttributeMaxDynamicSharedMemorySize, AT_SMEM);

    // 1) operand prep
    split_rows<<<(MROWS * KDIM / 4) / 256, 256>>>(x, x2);
    castT<<<dim3(QKVN / 32, KDIM / 32), 256>>>(w_qkv, wq2, QKVN);
    castT<<<dim3(EMBED / 32, KDIM / 32), 256>>>(w_out, wo2, EMBED);

    // 2) QKV projection (A split 2-term) -> single fp16 qkv
    mma_gemm<true, true><<<dim3(QKVN / BN, MROWS / BM), 256, smem1>>>(
        x2, wq2, b_qkv, qkv1, QKVN);

    // 3) tensor-core flash attention (all single fp16) -> fp16 att
    attn_mma<<<dim3(SEQ / 128, NHEAD, BATCH), 256, AT_SMEM>>>(qkv1, att1);

    // 4) output projection (A single 1-term) -> fp32 out
    mma_gemm<false, false><<<dim3(EMBED / BN, MROWS / BM), 256, smem2>>>(
        att1, wo2, b_out, out, EMBED);
}

// round 10
// speedup vs baseline: 1.9829x; 1.4176x over previous
#include <cuda_runtime.h>
#include <cuda_fp16.h>
#include <cstdint>

#define EMBED   1024
#define NHEAD   16
#define HD      64
#define SEQ     2048
#define BATCH   4
#define MROWS   (BATCH * SEQ)      /* 8192 */
#define QKVN    (3 * EMBED)        /* 3072 */
#define KDIM    1024

// ---------------------------------------------------------------------------
// Scratch (device globals -- runtime allocation is forbidden)
// ---------------------------------------------------------------------------
static __device__ __half g_x1  [(size_t)MROWS * KDIM];       // x fp16
static __device__ __half g_qkv1[(size_t)MROWS * QKVN];       // qkv fp16
static __device__ __half g_att1[(size_t)MROWS * KDIM];       // attn out fp16
static __device__ __half g_wq2 [(size_t)QKVN  * KDIM];       // w_qkv^T fp16
static __device__ __half g_wo2 [(size_t)EMBED * KDIM];       // w_out^T fp16

// ---------------------------------------------------------------------------
// PTX helpers (baseline ISA, sm_80-compatible encodings only)
// ---------------------------------------------------------------------------
__device__ __forceinline__ uint32_t smem_u32(const void* p) {
    uint32_t a;
    asm("{ .reg .u64 t; cvta.to.shared.u64 t, %1; cvt.u32.u64 %0, t; }"
        : "=r"(a) : "l"(p));
    return a;
}
__device__ __forceinline__ void cpasync16(uint32_t dst, const void* src) {
    asm volatile("cp.async.cg.shared.global [%0], [%1], 16;"
        :: "r"(dst), "l"(src) : "memory");
}
#define CP_COMMIT() asm volatile("cp.async.commit_group;" ::: "memory")

__device__ __forceinline__ void ldsm4(uint32_t* r, uint32_t addr) {
    asm volatile("ldmatrix.sync.aligned.m8n8.x4.shared.b16 {%0,%1,%2,%3}, [%4];"
        : "=r"(r[0]), "=r"(r[1]), "=r"(r[2]), "=r"(r[3]) : "r"(addr));
}
__device__ __forceinline__ void ldsm4t(uint32_t* r, uint32_t addr) {
    asm volatile("ldmatrix.sync.aligned.m8n8.x4.trans.shared.b16 {%0,%1,%2,%3}, [%4];"
        : "=r"(r[0]), "=r"(r[1]), "=r"(r[2]), "=r"(r[3]) : "r"(addr));
}
// fp16 MMA, fp32 accumulate
__device__ __forceinline__ void mma16816(float* c, const uint32_t* a,
                                         uint32_t b0, uint32_t b1) {
    asm volatile(
        "mma.sync.aligned.m16n8k16.row.col.f32.f16.f16.f32 "
        "{%0,%1,%2,%3}, {%4,%5,%6,%7}, {%8,%9}, {%0,%1,%2,%3};"
        : "+f"(c[0]), "+f"(c[1]), "+f"(c[2]), "+f"(c[3])
        : "r"(a[0]), "r"(a[1]), "r"(a[2]), "r"(a[3]), "r"(b0), "r"(b1));
}
__device__ __forceinline__ float ex2(float x) {
    float y; asm("ex2.approx.f32 %0, %1;" : "=f"(y) : "f"(x)); return y;
}
__device__ __forceinline__ uint32_t pack_h2(float x, float y) {
    __half2 h = __floats2half2_rn(x, y);
    return *(uint32_t*)&h;
}

// ---------------------------------------------------------------------------
// operand prep
// ---------------------------------------------------------------------------
// in [M, K] fp32 -> out [M, K] fp16
__global__ void cast_rows(const float* __restrict__ in, __half* __restrict__ out) {
    size_t i4 = (size_t)blockIdx.x * blockDim.x + threadIdx.x;
    float4 v = *(const float4*)(in + i4 * 4);
    __half2 a = __floats2half2_rn(v.x, v.y);
    __half2 b = __floats2half2_rn(v.z, v.w);
    *(__half2*)(out + i4 * 4)     = a;
    *(__half2*)(out + i4 * 4 + 2) = b;
}

// w [K, N] fp32 -> out [N, K] fp16 (transpose + cast)
__global__ __launch_bounds__(256) void castT(const float* __restrict__ w,
                                             __half* __restrict__ out, int N) {
    __shared__ float t[32][33];
    const int tid = threadIdx.x;
    const int tx = tid & 31, ty = tid >> 5;
    const int n0 = blockIdx.x * 32, k0 = blockIdx.y * 32;
#pragma unroll
    for (int i = 0; i < 4; i++)
        t[ty + 8 * i][tx] = w[(size_t)(k0 + ty + 8 * i) * N + n0 + tx];
    __syncthreads();
#pragma unroll
    for (int i = 0; i < 4; i++) {
        int nl = ty + 8 * i;
        out[(size_t)(n0 + nl) * KDIM + k0 + tx] = __float2half_rn(t[tx][nl]);
    }
}

// ---------------------------------------------------------------------------
// mma.sync fp16 GEMM (single term). CTA 128x128, warp tile 64x32 (2Mx4N),
// BK=64, 3-stage cp.async. Stage 32KB: A 16K | B 16K. 96KB -> 2 CTA/SM.
// Rows 128B, chunk swizzle c^(r&7).
// SPLIT=true : C fp16 [M,ldc] + bias.   SPLIT=false: C fp32 [M,ldc] + bias.
// ---------------------------------------------------------------------------
#define BM 128
#define BN 128
#define BK 64
#define NK (KDIM / BK)            /* 16 */
#define NSTAGE 3
#define STG_BYTES 32768
#define GEMM_SMEM (NSTAGE * STG_BYTES)   /* 98304 */

__device__ __forceinline__ void gemm_load_stage(
    uint32_t sbase, const __half* __restrict__ A, const __half* __restrict__ B1,
    int m0, int n0, int kt, int tid)
{
    const int k0 = kt * BK;
#pragma unroll
    for (int i = 0; i < 4; i++) {
        int id = tid + 256 * i;            // 0..1023: 128 rows x 8 chunks
        int r = id >> 3;
        int c = id & 7;
        uint32_t soff = r * 128 + ((c ^ (r & 7)) << 4);
        cpasync16(sbase + soff,         A  + (size_t)(m0 + r) * KDIM + k0 + c * 8);
        cpasync16(sbase + 16384 + soff, B1 + (size_t)(n0 + r) * KDIM + k0 + c * 8);
    }
}

template<bool SPLIT>
__global__ __launch_bounds__(256, 2) void mma_gemm(
    const __half* __restrict__ A, const __half* __restrict__ B1,
    const float* __restrict__ bias, void* __restrict__ Cv, int ldc)
{
    extern __shared__ char sm[];
    const uint32_t sb = smem_u32(sm);
    const int tid  = threadIdx.x;
    const int lane = tid & 31;
    const int wid  = tid >> 5;
    const int wm   = wid & 1;
    const int wn   = wid >> 1;
    const int m0 = blockIdx.y * BM;
    const int n0 = blockIdx.x * BN;

    const int lrow  = lane & 15;
    const int lhalf = lane >> 4;
    const int xorv  = lrow & 7;

    uint32_t arow[4], brow[2];
#pragma unroll
    for (int mt = 0; mt < 4; mt++) arow[mt] = (wm * 64 + mt * 16 + lrow) * 128;
#pragma unroll
    for (int nt2 = 0; nt2 < 2; nt2++)
        brow[nt2] = 16384u + (wn * 32 + nt2 * 16 + lrow) * 128;

    float acc[4][4][4];
#pragma unroll
    for (int i = 0; i < 4; i++)
#pragma unroll
        for (int j = 0; j < 4; j++)
#pragma unroll
            for (int q = 0; q < 4; q++) acc[i][j][q] = 0.f;

    gemm_load_stage(sb,             A, B1, m0, n0, 0, tid); CP_COMMIT();
    gemm_load_stage(sb + STG_BYTES, A, B1, m0, n0, 1, tid); CP_COMMIT();

    for (int kt = 0; kt < NK; kt++) {
        if (kt < NK - 2) {
            gemm_load_stage(sb + ((kt + 2) % NSTAGE) * STG_BYTES, A, B1, m0, n0, kt + 2, tid);
            CP_COMMIT();
            asm volatile("cp.async.wait_group 2;" ::: "memory");
        } else if (kt == NK - 2) {
            asm volatile("cp.async.wait_group 1;" ::: "memory");
        } else {
            asm volatile("cp.async.wait_group 0;" ::: "memory");
        }
        __syncthreads();

        const uint32_t st = sb + (kt % NSTAGE) * STG_BYTES;
#pragma unroll
        for (int ks = 0; ks < 4; ks++) {
            const uint32_t coff = (uint32_t)(((ks * 2 + lhalf) ^ xorv) << 4);
            uint32_t ah[4][4], bh[2][4];
#pragma unroll
            for (int mt = 0; mt < 4; mt++) ldsm4(ah[mt], st + arow[mt] + coff);
#pragma unroll
            for (int nt2 = 0; nt2 < 2; nt2++) ldsm4(bh[nt2], st + brow[nt2] + coff);
#pragma unroll
            for (int mt = 0; mt < 4; mt++)
#pragma unroll
                for (int nt = 0; nt < 4; nt++) {
                    const int n2 = nt >> 1, sel = nt & 1;
                    mma16816(acc[mt][nt], ah[mt], bh[n2][sel], bh[n2][sel + 2]);
                }
        }
        __syncthreads();
    }

#pragma unroll
    for (int nt = 0; nt < 4; nt++) {
        const int col = n0 + wn * 32 + nt * 8 + (lane & 3) * 2;
        const float bx = __ldg(bias + col);
        const float by = __ldg(bias + col + 1);
#pragma unroll
        for (int mt = 0; mt < 4; mt++) {
            const int row = m0 + wm * 64 + mt * 16 + (lane >> 2);
            if (SPLIT) {
                __half* Cb = (__half*)Cv;
                *(uint32_t*)(Cb + (size_t)row * ldc + col) =
                    pack_h2(acc[mt][nt][0] + bx, acc[mt][nt][1] + by);
                *(uint32_t*)(Cb + (size_t)(row + 8) * ldc + col) =
                    pack_h2(acc[mt][nt][2] + bx, acc[mt][nt][3] + by);
            } else {
                float* C = (float*)Cv;
                float2 v0 = make_float2(acc[mt][nt][0] + bx, acc[mt][nt][1] + by);
                float2 v1 = make_float2(acc[mt][nt][2] + bx, acc[mt][nt][3] + by);
                *(float2*)(C + (size_t)row * ldc + col)       = v0;
                *(float2*)(C + (size_t)(row + 8) * ldc + col) = v1;
            }
        }
    }
}

// ---------------------------------------------------------------------------
// Tensor-core flash attention, all-fp16 operands -- unchanged from R9.
// Per CTA: 128 q-rows, one (b,h). 8 warps x 16 rows. Key tiles of 64.
// smem: Q 16K | 2 stages of {K 8K | V 8K} = 48KB -> 2 CTAs/SM.
// qkv1 row layout: [q(1024) k(1024) v(1024)], row stride 3072.
// ---------------------------------------------------------------------------
#define AT_SMEM (16384 + 2 * 16384)   /* 49152 */
#define C1 0.18033688f                /* 0.125 * log2(e) */

__device__ __forceinline__ void attn_load_kv(
    uint32_t stage, const __half* __restrict__ kvb, int tid)
{
#pragma unroll
    for (int i = 0; i < 2; i++) {
        int id = tid + 256 * i;            // 0..511 -> 64 rows x 8 chunks
        int r = id >> 3, c = id & 7;
        uint32_t soff = r * 128 + ((c ^ (r & 7)) << 4);
        const __half* g = kvb + (size_t)r * 3072 + c * 8;
        cpasync16(stage +        soff, g + 1024);   // K
        cpasync16(stage + 8192 + soff, g + 2048);   // V
    }
}

__global__ __launch_bounds__(256, 2) void attn_mma(
    const __half* __restrict__ qkv1, __half* __restrict__ att1)
{
    extern __shared__ char sm[];
    const uint32_t sb = smem_u32(sm);
    const uint32_t Qs = sb, ST0 = sb + 16384;

    const int tid = threadIdx.x, lane = tid & 31, wid = tid >> 5;
    const int qb = blockIdx.x, h = blockIdx.y, b = blockIdx.z;
    const int lrow = lane & 15, lhalf = lane >> 4;
    const size_t rowbase = (size_t)b * SEQ;
    const __half* qg  = qkv1 + (rowbase + qb * 128) * 3072 + h * 64;
    const __half* kvg = qkv1 + rowbase * 3072 + h * 64;

    // Q tile load
#pragma unroll
    for (int i = 0; i < 4; i++) {
        int id = tid + 256 * i;            // 0..1023 -> 128 rows x 8 chunks
        int r = id >> 3, c = id & 7;
        uint32_t soff = r * 128 + ((c ^ (r & 7)) << 4);
        cpasync16(Qs + soff, qg + (size_t)r * 3072 + c * 8);
    }
    CP_COMMIT();
    attn_load_kv(ST0,         kvg,             tid); CP_COMMIT();
    attn_load_kv(ST0 + 16384, kvg + 64 * 3072, tid); CP_COMMIT();

    // Q fragments to registers
    asm volatile("cp.async.wait_group 2;" ::: "memory");
    __syncthreads();
    uint32_t qf[4][4];
    {
        int r = wid * 16 + lrow;
        uint32_t ro = (uint32_t)r * 128;
        int xv = r & 7;
#pragma unroll
        for (int ds = 0; ds < 4; ds++) {
            uint32_t co = (uint32_t)(((ds * 2 + lhalf) ^ xv) << 4);
            ldsm4(qf[ds], Qs + ro + co);
        }
    }

    float oacc[8][4];
#pragma unroll
    for (int t = 0; t < 8; t++)
#pragma unroll
        for (int q = 0; q < 4; q++) oacc[t][q] = 0.f;
    float m0 = -1e30f, m1 = -1e30f, l0 = 0.f, l1 = 0.f;

    const int kxv = lrow & 7;
    for (int kt = 0; kt < 32; kt++) {
        if (kt == 31) asm volatile("cp.async.wait_group 0;" ::: "memory");
        else          asm volatile("cp.async.wait_group 1;" ::: "memory");
        __syncthreads();
        const uint32_t st = ST0 + (uint32_t)(kt & 1) * 16384;

        // ---- S = Q K^T
        float sacc[8][4];
#pragma unroll
        for (int t = 0; t < 8; t++)
#pragma unroll
            for (int q = 0; q < 4; q++) sacc[t][q] = 0.f;

#pragma unroll
        for (int ds = 0; ds < 4; ds++) {
            uint32_t kh[4][4];
            const uint32_t co = (uint32_t)(((ds * 2 + lhalf) ^ kxv) << 4);
#pragma unroll
            for (int g = 0; g < 4; g++)
                ldsm4(kh[g], st + (uint32_t)(g * 16 + lrow) * 128 + co);
#pragma unroll
            for (int g = 0; g < 4; g++)
#pragma unroll
                for (int sel = 0; sel < 2; sel++)
                    mma16816(sacc[g * 2 + sel], qf[ds], kh[g][sel], kh[g][sel + 2]);
        }

        // ---- online softmax
        float mx0 = sacc[0][0], mx1 = sacc[0][2];
#pragma unroll
        for (int t = 0; t < 8; t++) {
            mx0 = fmaxf(mx0, fmaxf(sacc[t][0], sacc[t][1]));
            mx1 = fmaxf(mx1, fmaxf(sacc[t][2], sacc[t][3]));
        }
        mx0 = fmaxf(mx0, __shfl_xor_sync(0xffffffffu, mx0, 1));
        mx0 = fmaxf(mx0, __shfl_xor_sync(0xffffffffu, mx0, 2));
        mx1 = fmaxf(mx1, __shfl_xor_sync(0xffffffffu, mx1, 1));
        mx1 = fmaxf(mx1, __shfl_xor_sync(0xffffffffu, mx1, 2));
        const float mn0 = fmaxf(m0, mx0), mn1 = fmaxf(m1, mx1);
        const float a0 = ex2((m0 - mn0) * C1), a1 = ex2((m1 - mn1) * C1);
        const float mc0 = mn0 * C1, mc1 = mn1 * C1;
        float ls0 = 0.f, ls1 = 0.f;
#pragma unroll
        for (int t = 0; t < 8; t++) {
            sacc[t][0] = ex2(fmaf(sacc[t][0], C1, -mc0));
            sacc[t][1] = ex2(fmaf(sacc[t][1], C1, -mc0));
            sacc[t][2] = ex2(fmaf(sacc[t][2], C1, -mc1));
            sacc[t][3] = ex2(fmaf(sacc[t][3], C1, -mc1));
            ls0 += sacc[t][0] + sacc[t][1];
            ls1 += sacc[t][2] + sacc[t][3];
        }
        ls0 += __shfl_xor_sync(0xffffffffu, ls0, 1);
        ls0 += __shfl_xor_sync(0xffffffffu, ls0, 2);
        ls1 += __shfl_xor_sync(0xffffffffu, ls1, 1);
        ls1 += __shfl_xor_sync(0xffffffffu, ls1, 2);
        m0 = mn0; m1 = mn1;
        l0 = l0 * a0 + ls0; l1 = l1 * a1 + ls1;
#pragma unroll
        for (int t = 0; t < 8; t++) {
            oacc[t][0] *= a0; oacc[t][1] *= a0;
            oacc[t][2] *= a1; oacc[t][3] *= a1;
        }

        // ---- O += P V
#pragma unroll
        for (int kg = 0; kg < 4; kg++) {
            uint32_t aph[4];
            {
                const float* t0 = sacc[2 * kg];
                const float* t1 = sacc[2 * kg + 1];
                aph[0] = pack_h2(t0[0], t0[1]);
                aph[1] = pack_h2(t0[2], t0[3]);
                aph[2] = pack_h2(t1[0], t1[1]);
                aph[3] = pack_h2(t1[2], t1[3]);
            }
            const uint32_t vro = st + 8192 + (uint32_t)(kg * 16 + lrow) * 128;
#pragma unroll
            for (int dg = 0; dg < 4; dg++) {
                uint32_t vh[4];
                ldsm4t(vh, vro + (uint32_t)(((dg * 2 + lhalf) ^ kxv) << 4));
#pragma unroll
                for (int sel = 0; sel < 2; sel++)
                    mma16816(oacc[dg * 2 + sel], aph, vh[2 * sel], vh[2 * sel + 1]);
            }
        }
        __syncthreads();
        if (kt + 2 < 32) {
            attn_load_kv(ST0 + (uint32_t)(kt & 1) * 16384,
                         kvg + (size_t)(kt + 2) * 64 * 3072, tid);
            CP_COMMIT();
        }
    }

    // ---- epilogue
    const float inv0 = 1.0f / l0, inv1 = 1.0f / l1;
    const size_t grow = rowbase + (size_t)qb * 128 + wid * 16 + (lane >> 2);
#pragma unroll
    for (int t = 0; t < 8; t++) {
        const int col = h * 64 + t * 8 + (lane & 3) * 2;
        *(uint32_t*)(att1 + grow * 1024 + col) =
            pack_h2(oacc[t][0] * inv0, oacc[t][1] * inv0);
        *(uint32_t*)(att1 + (grow + 8) * 1024 + col) =
            pack_h2(oacc[t][2] * inv1, oacc[t][3] * inv1);
    }
}

// ---------------------------------------------------------------------------
// Host side
// ---------------------------------------------------------------------------
extern "C" void kernel_launch(void* const* d_in, const int* in_sizes, int n_in,
                              void* d_out, int out_size)
{
    (void)in_sizes; (void)n_in; (void)out_size;
    const float* x     = (const float*)d_in[0];
    const float* w_qkv = (const float*)d_in[1];
    const float* b_qkv = (const float*)d_in[2];
    const float* w_out = (const float*)d_in[3];
    const float* b_out = (const float*)d_in[4];
    float* out = (float*)d_out;

    __half *x1, *qkv1, *att1, *wq2, *wo2;
    cudaGetSymbolAddress((void**)&x1,   g_x1);
    cudaGetSymbolAddress((void**)&qkv1, g_qkv1);
    cudaGetSymbolAddress((void**)&att1, g_att1);
    cudaGetSymbolAddress((void**)&wq2,  g_wq2);
    cudaGetSymbolAddress((void**)&wo2,  g_wo2);

    cudaFuncSetAttribute(mma_gemm<true>,
                         cudaFuncAttributeMaxDynamicSharedMemorySize, GEMM_SMEM);
    cudaFuncSetAttribute(mma_gemm<false>,
                         cudaFuncAttributeMaxDynamicSharedMemorySize, GEMM_SMEM);
    cudaFuncSetAttribute(attn_mma, cudaFuncAttributeMaxDynamicSharedMemorySize, AT_SMEM);

    // 1) operand prep (all single fp16)
    cast_rows<<<(MROWS * KDIM / 4) / 256, 256>>>(x, x1);
    castT<<<dim3(QKVN / 32, KDIM / 32), 256>>>(w_qkv, wq2, QKVN);
    castT<<<dim3(EMBED / 32, KDIM / 32), 256>>>(w_out, wo2, EMBED);

    // 2) QKV projection -> fp16 qkv
    mma_gemm<true><<<dim3(QKVN / BN, MROWS / BM), 256, GEMM_SMEM>>>(
        x1, wq2, b_qkv, qkv1, QKVN);

    // 3) tensor-core flash attention -> fp16 att
    attn_mma<<<dim3(SEQ / 128, NHEAD, BATCH), 256, AT_SMEM>>>(qkv1, att1);

    // 4) output projection -> fp32 out
    mma_gemm<false><<<dim3(EMBED / BN, MROWS / BM), 256, GEMM_SMEM>>>(
        att1, wo2, b_out, out, EMBED);
}